// round 6
// baseline (speedup 1.0000x reference)
#include <cuda_runtime.h>
#include <math.h>

// Problem constants
#define D        256
#define KC       8192
#define NR       16384
#define BM       128
#define BN       128
#define BD       16
#define SPLITS   4
#define KPER     (KC / SPLITS)      // 2048
#define NTILES   (KPER / BN)        // 16
#define ROWBLKS  (NR / BM)          // 128
#define NQBLKS   (NR / 8)           // 2048

#define AROW     (2 * BM + 4)       // 260 floats per d-row (duplicated pairs)
#define BROW     (BN + 4)           // 132 floats per d-row

// Output layout (concatenated, float32):
#define OFF_Q   16384
#define OFF_ST  4210688
#define OFF_SC  8404992

// Device scratch (no allocations allowed)
__device__ float g_xnorm[NR];
__device__ int   g_cand[NR * 16];
__device__ int   g_final[NR];
__device__ float g_hist[KC];
__device__ float g_partial[NQBLKS];

// ---------------- packed f32x2 helpers ----------------
__device__ __forceinline__ void unpack2(unsigned long long v, float& lo, float& hi) {
    asm("mov.b64 {%0, %1}, %2;" : "=f"(lo), "=f"(hi) : "l"(v));
}
__device__ __forceinline__ void ffma2(unsigned long long& acc,
                                      unsigned long long a2,
                                      unsigned long long b2) {
    asm("fma.rn.f32x2 %0, %1, %2, %0;" : "+l"(acc) : "l"(a2), "l"(b2));
}

// ---------------- kernel 0: zero histogram ----------------
__global__ void k_init() {
    int t = blockIdx.x * blockDim.x + threadIdx.x;
    if (t < KC) g_hist[t] = 0.0f;
}

// ---------------- kernel 1: latent row norms ----------------
__global__ void k_xnorm(const float* __restrict__ lat) {
    int w = (blockIdx.x * blockDim.x + threadIdx.x) >> 5;
    int lane = threadIdx.x & 31;
    if (w >= NR) return;
    const float4* p = reinterpret_cast<const float4*>(lat + (size_t)w * D);
    float s = 0.0f;
    float4 v0 = p[lane];
    float4 v1 = p[lane + 32];
    s += v0.x * v0.x + v0.y * v0.y + v0.z * v0.z + v0.w * v0.w;
    s += v1.x * v1.x + v1.y * v1.y + v1.z * v1.z + v1.w * v1.w;
    #pragma unroll
    for (int o = 16; o > 0; o >>= 1) s += __shfl_xor_sync(0xFFFFFFFFu, s, o);
    if (lane == 0) g_xnorm[w] = s;
}

// ---------------- kernel 2: GEMM (m = x.c) + per-split top-4 candidates
// smem hands FFMA2 operands pre-packed: A duplicated (a,a) pairs, B natural pairs.
__global__ __launch_bounds__(256, 2)
void k_argmin(const float* __restrict__ latents, const float* __restrict__ cb) {
    __shared__ union SH {
        struct { float A2[BD * AROW]; float B[BD * BROW]; } tiles;
        struct { float v[BM][32]; int idx[BM][32]; } red;
    } sh;

    const int split = blockIdx.y;
    const int row0  = blockIdx.x * BM;
    const int t  = threadIdx.x;
    const int tx = t & 15;     // code group (8 codes)
    const int ty = t >> 4;     // row group  (8 rows)

    // swizzled read offsets for this thread's two B 16B-blocks
    const int blk0 = 2 * tx;
    const int blk1 = 2 * tx + 1;
    const int sb0 = (blk0 ^ ((blk0 >> 3) & 1)) * 4;
    const int sb1 = (blk1 ^ ((blk1 >> 3) & 1)) * 4;

    // per-thread top-2 per row (ascending code order => strict > keeps lowest idx)
    float v1[8], v2[8];
    int   i1[8], i2[8];
    #pragma unroll
    for (int i = 0; i < 8; i++) {
        v1[i] = -3.4e38f; v2[i] = -3.4e38f;
        i1[i] = 0x7FFFFFFF; i2[i] = 0x7FFFFFFF;
    }

    for (int ct = 0; ct < NTILES; ct++) {
        const int c0 = split * KPER + ct * BN;

        unsigned long long acc[8][4];
        #pragma unroll
        for (int i = 0; i < 8; i++)
            #pragma unroll
            for (int j = 0; j < 4; j++) acc[i][j] = 0ull;

        for (int dk = 0; dk < D / BD; dk++) {
            __syncthreads();   // previous compute done before overwrite
            // A tile: duplicated pairs, transposed: A2[d][2*row] = (a, a)
            #pragma unroll
            for (int i = 0; i < 2; i++) {
                int vidx = t + i * 256;        // 0..511
                int row  = vidx >> 2;          // 0..127
                int dv   = vidx & 3;           // 0..3
                float4 v = *reinterpret_cast<const float4*>(
                    latents + (size_t)(row0 + row) * D + dk * BD + dv * 4);
                *reinterpret_cast<float2*>(&sh.tiles.A2[(dv * 4 + 0) * AROW + 2 * row]) = make_float2(v.x, v.x);
                *reinterpret_cast<float2*>(&sh.tiles.A2[(dv * 4 + 1) * AROW + 2 * row]) = make_float2(v.y, v.y);
                *reinterpret_cast<float2*>(&sh.tiles.A2[(dv * 4 + 2) * AROW + 2 * row]) = make_float2(v.z, v.z);
                *reinterpret_cast<float2*>(&sh.tiles.A2[(dv * 4 + 3) * AROW + 2 * row]) = make_float2(v.w, v.w);
            }
            // B tile: transposed with 16B-block swizzle
            #pragma unroll
            for (int i = 0; i < 2; i++) {
                int vidx = t + i * 256;
                int row  = vidx >> 2;          // code 0..127
                int dv   = vidx & 3;
                float4 v = *reinterpret_cast<const float4*>(
                    cb + (size_t)(c0 + row) * D + dk * BD + dv * 4);
                int blk = row >> 2;
                int win = row & 3;
                int col = ((blk ^ ((blk >> 3) & 1)) << 2) | win;
                sh.tiles.B[(dv * 4 + 0) * BROW + col] = v.x;
                sh.tiles.B[(dv * 4 + 1) * BROW + col] = v.y;
                sh.tiles.B[(dv * 4 + 2) * BROW + col] = v.z;
                sh.tiles.B[(dv * 4 + 3) * BROW + col] = v.w;
            }
            __syncthreads();

            #pragma unroll
            for (int k = 0; k < BD; k++) {
                const ulonglong2* pa = reinterpret_cast<const ulonglong2*>(
                    &sh.tiles.A2[k * AROW + 16 * ty]);
                ulonglong2 a01 = pa[0];
                ulonglong2 a23 = pa[1];
                ulonglong2 a45 = pa[2];
                ulonglong2 a67 = pa[3];
                ulonglong2 bA = *reinterpret_cast<const ulonglong2*>(&sh.tiles.B[k * BROW + sb0]);
                ulonglong2 bB = *reinterpret_cast<const ulonglong2*>(&sh.tiles.B[k * BROW + sb1]);
                unsigned long long av[8] = { a01.x, a01.y, a23.x, a23.y,
                                             a45.x, a45.y, a67.x, a67.y };
                unsigned long long bv[4] = { bA.x, bA.y, bB.x, bB.y };
                #pragma unroll
                for (int i = 0; i < 8; i++)
                    #pragma unroll
                    for (int j = 0; j < 4; j++) ffma2(acc[i][j], av[i], bv[j]);
            }
        }

        // fold into per-thread top-2 (ascending code order)
        #pragma unroll
        for (int i = 0; i < 8; i++) {
            #pragma unroll
            for (int j = 0; j < 4; j++) {
                float lo, hi;
                unpack2(acc[i][j], lo, hi);
                int c = c0 + tx * 8 + j * 2;
                if (lo > v1[i])      { v2[i]=v1[i]; i2[i]=i1[i]; v1[i]=lo; i1[i]=c; }
                else if (lo > v2[i]) { v2[i]=lo; i2[i]=c; }
                int c2 = c + 1;
                if (hi > v1[i])      { v2[i]=v1[i]; i2[i]=i1[i]; v1[i]=hi; i1[i]=c2; }
                else if (hi > v2[i]) { v2[i]=hi; i2[i]=c2; }
            }
        }
    }

    // dump 16 threads x 2 entries = 32 candidates per row, select top-4
    __syncthreads();
    #pragma unroll
    for (int i = 0; i < 8; i++) {
        int row = ty * 8 + i;
        sh.red.v[row][tx * 2]       = v1[i];
        sh.red.idx[row][tx * 2]     = i1[i];
        sh.red.v[row][tx * 2 + 1]   = v2[i];
        sh.red.idx[row][tx * 2 + 1] = i2[i];
    }
    __syncthreads();
    if (t < BM) {
        unsigned used = 0;
        int base = (row0 + t) * 16 + split * 4;
        #pragma unroll
        for (int s = 0; s < 4; s++) {
            float bv = -3.4e38f; int bidx = 0x7FFFFFFF; int bslot = 0;
            #pragma unroll
            for (int x = 0; x < 32; x++) {
                if ((used >> x) & 1u) continue;
                float v = sh.red.v[t][x];
                int  id = sh.red.idx[t][x];
                if (v > bv || (v == bv && id < bidx)) { bv = v; bidx = id; bslot = x; }
            }
            used |= 1u << bslot;
            g_cand[base + s] = bidx;
        }
    }
}

// ---------------- kernel 3: fp64 rescore, 4-way ILP over candidates.
// d = fl32(A - 2*m64), first-index ties -> order-independent compare.
__global__ void k_combine(const float* __restrict__ lat,
                          const float* __restrict__ cb) {
    int warp = threadIdx.x >> 5;
    int lane = threadIdx.x & 31;
    int r = blockIdx.x * 8 + warp;

    const float4* X = reinterpret_cast<const float4*>(lat + (size_t)r * D);
    float4 x0 = X[lane * 2];
    float4 x1 = X[lane * 2 + 1];
    double xd0 = x0.x, xd1 = x0.y, xd2 = x0.z, xd3 = x0.w;
    double xd4 = x1.x, xd5 = x1.y, xd6 = x1.z, xd7 = x1.w;
    double A = (double)g_xnorm[r];

    float bd = __int_as_float(0x7f800000);  // +inf
    int   bi = 0x7FFFFFFF;

    #pragma unroll
    for (int g = 0; g < 4; g++) {
        int c[4];
        #pragma unroll
        for (int q = 0; q < 4; q++) c[q] = g_cand[r * 16 + g * 4 + q];

        float4 r0[4], r1[4];
        #pragma unroll
        for (int q = 0; q < 4; q++) {
            const float4* C = reinterpret_cast<const float4*>(cb + (size_t)c[q] * D);
            r0[q] = C[lane * 2];
            r1[q] = C[lane * 2 + 1];
        }
        double m[4];
        #pragma unroll
        for (int q = 0; q < 4; q++) {
            m[q] = xd0 * (double)r0[q].x + xd1 * (double)r0[q].y
                 + xd2 * (double)r0[q].z + xd3 * (double)r0[q].w
                 + xd4 * (double)r1[q].x + xd5 * (double)r1[q].y
                 + xd6 * (double)r1[q].z + xd7 * (double)r1[q].w;
        }
        #pragma unroll
        for (int o = 16; o > 0; o >>= 1) {
            #pragma unroll
            for (int q = 0; q < 4; q++)
                m[q] += __shfl_xor_sync(0xFFFFFFFFu, m[q], o);
        }
        #pragma unroll
        for (int q = 0; q < 4; q++) {
            float d = (float)(A - 2.0 * m[q]);
            if (d < bd || (d == bd && c[q] < bi)) { bd = d; bi = c[q]; }
        }
    }
    if (lane == 0) g_final[r] = bi;
}

// ---------------- kernel 4: gather + outputs + partial losses + histogram
__global__ void k_quant(const float* __restrict__ latents,
                        const float* __restrict__ mask,
                        const float* __restrict__ cb,
                        float* __restrict__ out) {
    int warp = threadIdx.x >> 5;
    int lane = threadIdx.x & 31;
    int r = blockIdx.x * 8 + warp;

    int bi = g_final[r];

    const float4* L = reinterpret_cast<const float4*>(latents + (size_t)r * D);
    const float4* Q = reinterpret_cast<const float4*>(cb + (size_t)bi * D);
    float4* outq = reinterpret_cast<float4*>(out + OFF_Q  + (size_t)r * D);
    float4* outs = reinterpret_cast<float4*>(out + OFF_ST + (size_t)r * D);

    float ss = 0.0f;
    #pragma unroll
    for (int i = 0; i < 2; i++) {
        int idx = lane + 32 * i;
        float4 l = L[idx];
        float4 q = Q[idx];
        float4 st;
        st.x = __fadd_rn(l.x, __fsub_rn(q.x, l.x));
        st.y = __fadd_rn(l.y, __fsub_rn(q.y, l.y));
        st.z = __fadd_rn(l.z, __fsub_rn(q.z, l.z));
        st.w = __fadd_rn(l.w, __fsub_rn(q.w, l.w));
        outq[idx] = q;
        outs[idx] = st;
        float dx = l.x - q.x, dy = l.y - q.y, dz = l.z - q.z, dw = l.w - q.w;
        ss += dx * dx + dy * dy + dz * dz + dw * dw;
    }
    #pragma unroll
    for (int o = 16; o > 0; o >>= 1) ss += __shfl_xor_sync(0xFFFFFFFFu, ss, o);

    __shared__ float ws[8];
    if (lane == 0) {
        ws[warp] = ss;
        out[r] = (float)bi;
        atomicAdd(&g_hist[bi], mask[r]);
    }
    __syncthreads();
    if (threadIdx.x == 0) {
        float a = 0.0f;
        #pragma unroll
        for (int i = 0; i < 8; i++) a += ws[i];
        g_partial[blockIdx.x] = a;
    }
}

// ---------------- kernel 5: scalars (losses + perplexity) ----------------
__global__ void k_final(const float* __restrict__ mask, float* __restrict__ out) {
    __shared__ float red[256];
    int t = threadIdx.x;

    float s = 0.0f;
    for (int i = t; i < NR; i += 256) s += mask[i];
    red[t] = s; __syncthreads();
    for (int o = 128; o > 0; o >>= 1) { if (t < o) red[t] += red[t + o]; __syncthreads(); }
    float denom = fmaxf(red[0], 1.0f);
    __syncthreads();

    float q = 0.0f;
    for (int i = t; i < NQBLKS; i += 256) q += g_partial[i];
    red[t] = q; __syncthreads();
    for (int o = 128; o > 0; o >>= 1) { if (t < o) red[t] += red[t + o]; __syncthreads(); }
    float sq = red[0];
    __syncthreads();

    float e = 0.0f;
    for (int i = t; i < KC; i += 256) {
        float p = g_hist[i] / denom;
        e += p * logf(p + 1e-8f);
    }
    red[t] = e; __syncthreads();
    for (int o = 128; o > 0; o >>= 1) { if (t < o) red[t] += red[t + o]; __syncthreads(); }

    if (t == 0) {
        float mean = sq * (1.0f / 4194304.0f);
        out[OFF_SC + 0] = mean * 0.25f;
        out[OFF_SC + 1] = mean;
        out[OFF_SC + 2] = expf(-red[0]);
    }
}

extern "C" void kernel_launch(void* const* d_in, const int* in_sizes, int n_in,
                              void* d_out, int out_size) {
    const float* latents = (const float*)d_in[0];
    const float* mask    = (const float*)d_in[1];
    const float* cb      = (const float*)d_in[2];
    float* out = (float*)d_out;

    k_init<<<(KC + 255) / 256, 256>>>();
    k_xnorm<<<(NR * 32) / 256, 256>>>(latents);
    dim3 grid(ROWBLKS, SPLITS);
    k_argmin<<<grid, 256>>>(latents, cb);
    k_combine<<<NQBLKS, 256>>>(latents, cb);
    k_quant<<<NQBLKS, 256>>>(latents, mask, cb, out);
    k_final<<<1, 256>>>(mask, out);
}

// round 7
// speedup vs baseline: 1.1037x; 1.1037x over previous
#include <cuda_runtime.h>
#include <math.h>

// Problem constants
#define D        256
#define KC       8192
#define NR       16384
#define BM       128
#define BN       128
#define BD       32
#define SPLITS   4
#define KPER     (KC / SPLITS)      // 2048
#define NTILES   (KPER / BN)        // 16
#define ROWBLKS  (NR / BM)          // 128
#define NQBLKS   (NR / 8)           // 2048

// Output layout (concatenated, float32):
#define OFF_Q   16384
#define OFF_ST  4210688
#define OFF_SC  8404992

// Device scratch (no allocations allowed)
__device__ float g_xnorm[NR];
__device__ int   g_cand[NR * 16];
__device__ int   g_final[NR];
__device__ float g_hist[KC];
__device__ float g_partial[NQBLKS];

// ---------------- packed f32x2 helpers ----------------
__device__ __forceinline__ unsigned long long pack2(float lo, float hi) {
    unsigned long long r;
    asm("mov.b64 %0, {%1, %2};" : "=l"(r) : "f"(lo), "f"(hi));
    return r;
}
__device__ __forceinline__ void unpack2(unsigned long long v, float& lo, float& hi) {
    asm("mov.b64 {%0, %1}, %2;" : "=f"(lo), "=f"(hi) : "l"(v));
}
__device__ __forceinline__ void ffma2(unsigned long long& acc,
                                      unsigned long long a2,
                                      unsigned long long b2) {
    asm("fma.rn.f32x2 %0, %1, %2, %0;" : "+l"(acc) : "l"(a2), "l"(b2));
}

// ---------------- kernel 0: zero histogram ----------------
__global__ void k_init() {
    int t = blockIdx.x * blockDim.x + threadIdx.x;
    if (t < KC) g_hist[t] = 0.0f;
}

// ---------------- kernel 1: latent row norms ----------------
__global__ void k_xnorm(const float* __restrict__ lat) {
    int w = (blockIdx.x * blockDim.x + threadIdx.x) >> 5;
    int lane = threadIdx.x & 31;
    if (w >= NR) return;
    const float4* p = reinterpret_cast<const float4*>(lat + (size_t)w * D);
    float s = 0.0f;
    float4 v0 = p[lane];
    float4 v1 = p[lane + 32];
    s += v0.x * v0.x + v0.y * v0.y + v0.z * v0.z + v0.w * v0.w;
    s += v1.x * v1.x + v1.y * v1.y + v1.z * v1.z + v1.w * v1.w;
    #pragma unroll
    for (int o = 16; o > 0; o >>= 1) s += __shfl_xor_sync(0xFFFFFFFFu, s, o);
    if (lane == 0) g_xnorm[w] = s;
}

// ---------------- kernel 2: GEMM (pure dot m = x.c) + per-split top-4 candidates
// (round-5 version, measured 1720 us)
__global__ __launch_bounds__(256, 2)
void k_argmin(const float* __restrict__ latents, const float* __restrict__ cb) {
    __shared__ union SH {
        struct { float A[BD][BM + 4]; float B[BD][BN + 4]; } tiles;
        struct { float v[BM][32]; int idx[BM][32]; } red;
    } sh;

    const int split = blockIdx.y;
    const int row0  = blockIdx.x * BM;
    const int t  = threadIdx.x;
    const int tx = t & 15;     // code group (8 codes)
    const int ty = t >> 4;     // row group  (8 rows)

    // per-thread top-2 per row (ascending code order => strict > keeps lowest idx)
    float v1[8], v2[8];
    int   i1[8], i2[8];
    #pragma unroll
    for (int i = 0; i < 8; i++) {
        v1[i] = -3.4e38f; v2[i] = -3.4e38f;
        i1[i] = 0x7FFFFFFF; i2[i] = 0x7FFFFFFF;
    }

    for (int ct = 0; ct < NTILES; ct++) {
        const int c0 = split * KPER + ct * BN;

        unsigned long long acc[8][4];
        #pragma unroll
        for (int i = 0; i < 8; i++)
            #pragma unroll
            for (int j = 0; j < 4; j++) acc[i][j] = 0ull;

        for (int dk = 0; dk < D / BD; dk++) {
            __syncthreads();   // previous compute done before overwrite
            #pragma unroll
            for (int i = 0; i < 4; i++) {
                int vidx = t + i * 256;
                int row  = vidx >> 3;
                int dv   = vidx & 7;
                float4 v = *reinterpret_cast<const float4*>(
                    latents + (size_t)(row0 + row) * D + dk * BD + dv * 4);
                sh.tiles.A[dv * 4 + 0][row] = v.x;
                sh.tiles.A[dv * 4 + 1][row] = v.y;
                sh.tiles.A[dv * 4 + 2][row] = v.z;
                sh.tiles.A[dv * 4 + 3][row] = v.w;
            }
            #pragma unroll
            for (int i = 0; i < 4; i++) {
                int vidx = t + i * 256;
                int row  = vidx >> 3;
                int dv   = vidx & 7;
                float4 v = *reinterpret_cast<const float4*>(
                    cb + (size_t)(c0 + row) * D + dk * BD + dv * 4);
                sh.tiles.B[dv * 4 + 0][row] = v.x;
                sh.tiles.B[dv * 4 + 1][row] = v.y;
                sh.tiles.B[dv * 4 + 2][row] = v.z;
                sh.tiles.B[dv * 4 + 3][row] = v.w;
            }
            __syncthreads();

            #pragma unroll
            for (int k = 0; k < BD; k++) {
                float4 a0 = *reinterpret_cast<const float4*>(&sh.tiles.A[k][ty * 8]);
                float4 a1 = *reinterpret_cast<const float4*>(&sh.tiles.A[k][ty * 8 + 4]);
                float4 b0 = *reinterpret_cast<const float4*>(&sh.tiles.B[k][tx * 8]);
                float4 b1 = *reinterpret_cast<const float4*>(&sh.tiles.B[k][tx * 8 + 4]);
                unsigned long long bb[4] = {
                    pack2(b0.x, b0.y), pack2(b0.z, b0.w),
                    pack2(b1.x, b1.y), pack2(b1.z, b1.w) };
                float aa[8] = { a0.x, a0.y, a0.z, a0.w, a1.x, a1.y, a1.z, a1.w };
                #pragma unroll
                for (int i = 0; i < 8; i++) {
                    unsigned long long as = pack2(aa[i], aa[i]);
                    #pragma unroll
                    for (int j = 0; j < 4; j++) ffma2(acc[i][j], as, bb[j]);
                }
            }
        }

        // fold into per-thread top-2 (ascending code order)
        #pragma unroll
        for (int i = 0; i < 8; i++) {
            #pragma unroll
            for (int j = 0; j < 4; j++) {
                float lo, hi;
                unpack2(acc[i][j], lo, hi);
                int c = c0 + tx * 8 + j * 2;
                if (lo > v1[i])      { v2[i]=v1[i]; i2[i]=i1[i]; v1[i]=lo; i1[i]=c; }
                else if (lo > v2[i]) { v2[i]=lo; i2[i]=c; }
                int c2 = c + 1;
                if (hi > v1[i])      { v2[i]=v1[i]; i2[i]=i1[i]; v1[i]=hi; i1[i]=c2; }
                else if (hi > v2[i]) { v2[i]=hi; i2[i]=c2; }
            }
        }
    }

    // dump 16 threads x 2 entries = 32 candidates per row, select top-4
    __syncthreads();
    #pragma unroll
    for (int i = 0; i < 8; i++) {
        int row = ty * 8 + i;
        sh.red.v[row][tx * 2]       = v1[i];
        sh.red.idx[row][tx * 2]     = i1[i];
        sh.red.v[row][tx * 2 + 1]   = v2[i];
        sh.red.idx[row][tx * 2 + 1] = i2[i];
    }
    __syncthreads();
    if (t < BM) {
        unsigned used = 0;
        int base = (row0 + t) * 16 + split * 4;
        #pragma unroll
        for (int s = 0; s < 4; s++) {
            float bv = -3.4e38f; int bidx = 0x7FFFFFFF; int bslot = 0;
            #pragma unroll
            for (int x = 0; x < 32; x++) {
                if ((used >> x) & 1u) continue;
                float v = sh.red.v[t][x];
                int  id = sh.red.idx[t][x];
                if (v > bv || (v == bv && id < bidx)) { bv = v; bidx = id; bslot = x; }
            }
            used |= 1u << bslot;
            g_cand[base + s] = bidx;
        }
    }
}

// ---------------- kernel 3: fp64 rescore, restructured.
// One warp per row. Per pass: 2 candidates, 16 lanes each; lane handles 16
// interleaved dims (dims q*64 + (lane&15)*4 + 0..3, q = 0..3) so warp loads
// are lane-contiguous (4 lines per LDG). x kept in registers as doubles.
// d = fl32(fma(-2, m64, A)) -> identical rounding to fl32(A - 2*m64).
__global__ void k_combine(const float* __restrict__ lat,
                          const float* __restrict__ cb) {
    int warp = threadIdx.x >> 5;
    int lane = threadIdx.x & 31;
    int r = blockIdx.x * 8 + warp;
    int l16 = lane & 15;
    int half = lane >> 4;      // 0: even candidate of pair, 1: odd

    // preload this lane's 16 x dims (interleaved layout) as doubles
    const float4* X = reinterpret_cast<const float4*>(lat + (size_t)r * D);
    double xd[16];
    #pragma unroll
    for (int q = 0; q < 4; q++) {
        float4 xv = X[q * 16 + l16];
        xd[q * 4 + 0] = xv.x; xd[q * 4 + 1] = xv.y;
        xd[q * 4 + 2] = xv.z; xd[q * 4 + 3] = xv.w;
    }
    double A = (double)g_xnorm[r];

    float bd = __int_as_float(0x7f800000);  // +inf
    int   bi = 0x7FFFFFFF;

    #pragma unroll
    for (int cp = 0; cp < 8; cp++) {
        int c = g_cand[r * 16 + 2 * cp + half];
        const float4* C = reinterpret_cast<const float4*>(cb + (size_t)c * D);

        // batched loads (independent) then fp64 accumulate, 4 chains of 4
        float4 cv[4];
        #pragma unroll
        for (int q = 0; q < 4; q++) cv[q] = C[q * 16 + l16];

        double a0 = 0.0, a1 = 0.0, a2 = 0.0, a3 = 0.0;
        #pragma unroll
        for (int q = 0; q < 4; q++) {
            a0 = fma(xd[q * 4 + 0], (double)cv[q].x, a0);
            a1 = fma(xd[q * 4 + 1], (double)cv[q].y, a1);
            a2 = fma(xd[q * 4 + 2], (double)cv[q].z, a2);
            a3 = fma(xd[q * 4 + 3], (double)cv[q].w, a3);
        }
        double m = (a0 + a1) + (a2 + a3);
        // sum over the 16 lanes of this half (xor offsets 1,2,4,8 stay in-half)
        #pragma unroll
        for (int o = 1; o <= 8; o <<= 1)
            m += __shfl_xor_sync(0xFFFFFFFFu, m, o);

        float d = (float)fma(-2.0, m, A);
        if (d < bd || (d == bd && c < bi)) { bd = d; bi = c; }
    }

    // combine the two halves (all lanes of a half agree)
    float od = __shfl_xor_sync(0xFFFFFFFFu, bd, 16);
    int   oc = __shfl_xor_sync(0xFFFFFFFFu, bi, 16);
    if (od < bd || (od == bd && oc < bi)) { bd = od; bi = oc; }

    if (lane == 0) g_final[r] = bi;
}

// ---------------- kernel 4: gather + outputs + partial losses + histogram
__global__ void k_quant(const float* __restrict__ latents,
                        const float* __restrict__ mask,
                        const float* __restrict__ cb,
                        float* __restrict__ out) {
    int warp = threadIdx.x >> 5;
    int lane = threadIdx.x & 31;
    int r = blockIdx.x * 8 + warp;

    int bi = g_final[r];

    const float4* L = reinterpret_cast<const float4*>(latents + (size_t)r * D);
    const float4* Q = reinterpret_cast<const float4*>(cb + (size_t)bi * D);
    float4* outq = reinterpret_cast<float4*>(out + OFF_Q  + (size_t)r * D);
    float4* outs = reinterpret_cast<float4*>(out + OFF_ST + (size_t)r * D);

    float ss = 0.0f;
    #pragma unroll
    for (int i = 0; i < 2; i++) {
        int idx = lane + 32 * i;
        float4 l = L[idx];
        float4 q = Q[idx];
        float4 st;
        st.x = __fadd_rn(l.x, __fsub_rn(q.x, l.x));
        st.y = __fadd_rn(l.y, __fsub_rn(q.y, l.y));
        st.z = __fadd_rn(l.z, __fsub_rn(q.z, l.z));
        st.w = __fadd_rn(l.w, __fsub_rn(q.w, l.w));
        outq[idx] = q;
        outs[idx] = st;
        float dx = l.x - q.x, dy = l.y - q.y, dz = l.z - q.z, dw = l.w - q.w;
        ss += dx * dx + dy * dy + dz * dz + dw * dw;
    }
    #pragma unroll
    for (int o = 16; o > 0; o >>= 1) ss += __shfl_xor_sync(0xFFFFFFFFu, ss, o);

    __shared__ float ws[8];
    if (lane == 0) {
        ws[warp] = ss;
        out[r] = (float)bi;
        atomicAdd(&g_hist[bi], mask[r]);
    }
    __syncthreads();
    if (threadIdx.x == 0) {
        float a = 0.0f;
        #pragma unroll
        for (int i = 0; i < 8; i++) a += ws[i];
        g_partial[blockIdx.x] = a;
    }
}

// ---------------- kernel 5: scalars (losses + perplexity) ----------------
__global__ void k_final(const float* __restrict__ mask, float* __restrict__ out) {
    __shared__ float red[256];
    int t = threadIdx.x;

    float s = 0.0f;
    for (int i = t; i < NR; i += 256) s += mask[i];
    red[t] = s; __syncthreads();
    for (int o = 128; o > 0; o >>= 1) { if (t < o) red[t] += red[t + o]; __syncthreads(); }
    float denom = fmaxf(red[0], 1.0f);
    __syncthreads();

    float q = 0.0f;
    for (int i = t; i < NQBLKS; i += 256) q += g_partial[i];
    red[t] = q; __syncthreads();
    for (int o = 128; o > 0; o >>= 1) { if (t < o) red[t] += red[t + o]; __syncthreads(); }
    float sq = red[0];
    __syncthreads();

    float e = 0.0f;
    for (int i = t; i < KC; i += 256) {
        float p = g_hist[i] / denom;
        e += p * logf(p + 1e-8f);
    }
    red[t] = e; __syncthreads();
    for (int o = 128; o > 0; o >>= 1) { if (t < o) red[t] += red[t + o]; __syncthreads(); }

    if (t == 0) {
        float mean = sq * (1.0f / 4194304.0f);
        out[OFF_SC + 0] = mean * 0.25f;
        out[OFF_SC + 1] = mean;
        out[OFF_SC + 2] = expf(-red[0]);
    }
}

extern "C" void kernel_launch(void* const* d_in, const int* in_sizes, int n_in,
                              void* d_out, int out_size) {
    const float* latents = (const float*)d_in[0];
    const float* mask    = (const float*)d_in[1];
    const float* cb      = (const float*)d_in[2];
    float* out = (float*)d_out;

    k_init<<<(KC + 255) / 256, 256>>>();
    k_xnorm<<<(NR * 32) / 256, 256>>>(latents);
    dim3 grid(ROWBLKS, SPLITS);
    k_argmin<<<grid, 256>>>(latents, cb);
    k_combine<<<NQBLKS, 256>>>(latents, cb);
    k_quant<<<NQBLKS, 256>>>(latents, mask, cb, out);
    k_final<<<1, 256>>>(mask, out);
}

// round 17
// speedup vs baseline: 1.3051x; 1.1824x over previous
#include <cuda_runtime.h>
#include <math.h>

// Problem constants
#define D        256
#define KC       8192
#define NR       16384
#define BM       128
#define BN       128
#define BD       32
#define SPLITS   4
#define KPER     (KC / SPLITS)      // 2048
#define NTILES   (KPER / BN)        // 16
#define ROWBLKS  (NR / BM)          // 128
#define NQBLKS   (NR / 8)           // 2048

// Output layout (concatenated, float32):
#define OFF_Q   16384
#define OFF_ST  4210688
#define OFF_SC  8404992

// Device scratch (no allocations allowed)
__device__ float g_xnorm[NR];
__device__ int   g_cand[NR * 16];
__device__ int   g_final[NR];
__device__ float g_hist[KC];
__device__ float g_partial[NQBLKS];

// ---------------- packed f32x2 helpers ----------------
__device__ __forceinline__ unsigned long long pack2(float lo, float hi) {
    unsigned long long r;
    asm("mov.b64 %0, {%1, %2};" : "=l"(r) : "f"(lo), "f"(hi));
    return r;
}
__device__ __forceinline__ void unpack2(unsigned long long v, float& lo, float& hi) {
    asm("mov.b64 {%0, %1}, %2;" : "=f"(lo), "=f"(hi) : "l"(v));
}
__device__ __forceinline__ void ffma2(unsigned long long& acc,
                                      unsigned long long a2,
                                      unsigned long long b2) {
    asm("fma.rn.f32x2 %0, %1, %2, %0;" : "+l"(acc) : "l"(a2), "l"(b2));
}

// ---------------- exact fp32 transforms (never contracted: intrinsics only)
// TwoSum (Knuth): a + b = s + err exactly.
__device__ __forceinline__ void two_sum(float a, float b, float& s, float& err) {
    s = __fadd_rn(a, b);
    float z = __fsub_rn(s, a);
    err = __fadd_rn(__fsub_rn(a, __fsub_rn(s, z)), __fsub_rn(b, z));
}

// ---------------- kernel 0: zero histogram ----------------
__global__ void k_init() {
    int t = blockIdx.x * blockDim.x + threadIdx.x;
    if (t < KC) g_hist[t] = 0.0f;
}

// ---------------- kernel 1: latent row norms ----------------
__global__ void k_xnorm(const float* __restrict__ lat) {
    int w = (blockIdx.x * blockDim.x + threadIdx.x) >> 5;
    int lane = threadIdx.x & 31;
    if (w >= NR) return;
    const float4* p = reinterpret_cast<const float4*>(lat + (size_t)w * D);
    float s = 0.0f;
    float4 v0 = p[lane];
    float4 v1 = p[lane + 32];
    s += v0.x * v0.x + v0.y * v0.y + v0.z * v0.z + v0.w * v0.w;
    s += v1.x * v1.x + v1.y * v1.y + v1.z * v1.z + v1.w * v1.w;
    #pragma unroll
    for (int o = 16; o > 0; o >>= 1) s += __shfl_xor_sync(0xFFFFFFFFu, s, o);
    if (lane == 0) g_xnorm[w] = s;
}

// ---------------- kernel 2: GEMM (pure dot m = x.c) + per-split top-4 candidates
// (round-5 version, measured 1720 us — unchanged for attribution)
__global__ __launch_bounds__(256, 2)
void k_argmin(const float* __restrict__ latents, const float* __restrict__ cb) {
    __shared__ union SH {
        struct { float A[BD][BM + 4]; float B[BD][BN + 4]; } tiles;
        struct { float v[BM][32]; int idx[BM][32]; } red;
    } sh;

    const int split = blockIdx.y;
    const int row0  = blockIdx.x * BM;
    const int t  = threadIdx.x;
    const int tx = t & 15;     // code group (8 codes)
    const int ty = t >> 4;     // row group  (8 rows)

    float v1[8], v2[8];
    int   i1[8], i2[8];
    #pragma unroll
    for (int i = 0; i < 8; i++) {
        v1[i] = -3.4e38f; v2[i] = -3.4e38f;
        i1[i] = 0x7FFFFFFF; i2[i] = 0x7FFFFFFF;
    }

    for (int ct = 0; ct < NTILES; ct++) {
        const int c0 = split * KPER + ct * BN;

        unsigned long long acc[8][4];
        #pragma unroll
        for (int i = 0; i < 8; i++)
            #pragma unroll
            for (int j = 0; j < 4; j++) acc[i][j] = 0ull;

        for (int dk = 0; dk < D / BD; dk++) {
            __syncthreads();
            #pragma unroll
            for (int i = 0; i < 4; i++) {
                int vidx = t + i * 256;
                int row  = vidx >> 3;
                int dv   = vidx & 7;
                float4 v = *reinterpret_cast<const float4*>(
                    latents + (size_t)(row0 + row) * D + dk * BD + dv * 4);
                sh.tiles.A[dv * 4 + 0][row] = v.x;
                sh.tiles.A[dv * 4 + 1][row] = v.y;
                sh.tiles.A[dv * 4 + 2][row] = v.z;
                sh.tiles.A[dv * 4 + 3][row] = v.w;
            }
            #pragma unroll
            for (int i = 0; i < 4; i++) {
                int vidx = t + i * 256;
                int row  = vidx >> 3;
                int dv   = vidx & 7;
                float4 v = *reinterpret_cast<const float4*>(
                    cb + (size_t)(c0 + row) * D + dk * BD + dv * 4);
                sh.tiles.B[dv * 4 + 0][row] = v.x;
                sh.tiles.B[dv * 4 + 1][row] = v.y;
                sh.tiles.B[dv * 4 + 2][row] = v.z;
                sh.tiles.B[dv * 4 + 3][row] = v.w;
            }
            __syncthreads();

            #pragma unroll
            for (int k = 0; k < BD; k++) {
                float4 a0 = *reinterpret_cast<const float4*>(&sh.tiles.A[k][ty * 8]);
                float4 a1 = *reinterpret_cast<const float4*>(&sh.tiles.A[k][ty * 8 + 4]);
                float4 b0 = *reinterpret_cast<const float4*>(&sh.tiles.B[k][tx * 8]);
                float4 b1 = *reinterpret_cast<const float4*>(&sh.tiles.B[k][tx * 8 + 4]);
                unsigned long long bb[4] = {
                    pack2(b0.x, b0.y), pack2(b0.z, b0.w),
                    pack2(b1.x, b1.y), pack2(b1.z, b1.w) };
                float aa[8] = { a0.x, a0.y, a0.z, a0.w, a1.x, a1.y, a1.z, a1.w };
                #pragma unroll
                for (int i = 0; i < 8; i++) {
                    unsigned long long as = pack2(aa[i], aa[i]);
                    #pragma unroll
                    for (int j = 0; j < 4; j++) ffma2(acc[i][j], as, bb[j]);
                }
            }
        }

        #pragma unroll
        for (int i = 0; i < 8; i++) {
            #pragma unroll
            for (int j = 0; j < 4; j++) {
                float lo, hi;
                unpack2(acc[i][j], lo, hi);
                int c = c0 + tx * 8 + j * 2;
                if (lo > v1[i])      { v2[i]=v1[i]; i2[i]=i1[i]; v1[i]=lo; i1[i]=c; }
                else if (lo > v2[i]) { v2[i]=lo; i2[i]=c; }
                int c2 = c + 1;
                if (hi > v1[i])      { v2[i]=v1[i]; i2[i]=i1[i]; v1[i]=hi; i1[i]=c2; }
                else if (hi > v2[i]) { v2[i]=hi; i2[i]=c2; }
            }
        }
    }

    __syncthreads();
    #pragma unroll
    for (int i = 0; i < 8; i++) {
        int row = ty * 8 + i;
        sh.red.v[row][tx * 2]       = v1[i];
        sh.red.idx[row][tx * 2]     = i1[i];
        sh.red.v[row][tx * 2 + 1]   = v2[i];
        sh.red.idx[row][tx * 2 + 1] = i2[i];
    }
    __syncthreads();
    if (t < BM) {
        unsigned used = 0;
        int base = (row0 + t) * 16 + split * 4;
        #pragma unroll
        for (int s = 0; s < 4; s++) {
            float bv = -3.4e38f; int bidx = 0x7FFFFFFF; int bslot = 0;
            #pragma unroll
            for (int x = 0; x < 32; x++) {
                if ((used >> x) & 1u) continue;
                float v = sh.red.v[t][x];
                int  id = sh.red.idx[t][x];
                if (v > bv || (v == bv && id < bidx)) { bv = v; bidx = id; bslot = x; }
            }
            used |= 1u << bslot;
            g_cand[base + s] = bidx;
        }
    }
}

// ---------------- kernel 3: fp32 EFT rescore (NO fp64).
// One warp per row; 16 lanes per candidate, 2 candidates per pass.
// Dot2 compensated dot product: m = s + comp accurate to ~u^2.
// d = faithful fl32(A - 2m) via TwoSum; first-index ties.
__global__ void k_combine(const float* __restrict__ lat,
                          const float* __restrict__ cb) {
    int warp = threadIdx.x >> 5;
    int lane = threadIdx.x & 31;
    int r = blockIdx.x * 8 + warp;
    int l16 = lane & 15;
    int half = lane >> 4;

    // preload this lane's 16 x dims (interleaved layout)
    const float4* X = reinterpret_cast<const float4*>(lat + (size_t)r * D);
    float xf[16];
    #pragma unroll
    for (int q = 0; q < 4; q++) {
        float4 xv = X[q * 16 + l16];
        xf[q * 4 + 0] = xv.x; xf[q * 4 + 1] = xv.y;
        xf[q * 4 + 2] = xv.z; xf[q * 4 + 3] = xv.w;
    }
    float A = g_xnorm[r];

    float bd = __int_as_float(0x7f800000);  // +inf
    int   bi = 0x7FFFFFFF;

    #pragma unroll
    for (int cp = 0; cp < 8; cp++) {
        int c = g_cand[r * 16 + 2 * cp + half];
        const float4* C = reinterpret_cast<const float4*>(cb + (size_t)c * D);

        float4 cv[4];
        #pragma unroll
        for (int q = 0; q < 4; q++) cv[q] = C[q * 16 + l16];

        // dot2 over this lane's 16 elements
        float s = 0.0f, comp = 0.0f;
        #pragma unroll
        for (int q = 0; q < 4; q++) {
            float cf[4] = { cv[q].x, cv[q].y, cv[q].z, cv[q].w };
            #pragma unroll
            for (int e = 0; e < 4; e++) {
                float a = xf[q * 4 + e];
                float b = cf[e];
                float p  = __fmul_rn(a, b);
                float pe = __fmaf_rn(a, b, -p);          // exact product error
                float t, f;
                two_sum(s, p, t, f);
                s = t;
                comp = __fadd_rn(comp, __fadd_rn(f, pe));
            }
        }

        // reduce (s, comp) across the 16 lanes of this half with exact merges
        #pragma unroll
        for (int o = 1; o <= 8; o <<= 1) {
            float os = __shfl_xor_sync(0xFFFFFFFFu, s, o);
            float oc = __shfl_xor_sync(0xFFFFFFFFu, comp, o);
            float t, f;
            two_sum(s, os, t, f);
            s = t;
            comp = __fadd_rn(comp, __fadd_rn(oc, f));
        }

        // d = faithful fl32(A - 2*(s + comp))
        float nh = __fmul_rn(-2.0f, s);     // exact (scale by 2)
        float nl = __fmul_rn(-2.0f, comp);  // exact
        float t1, e1;
        two_sum(A, nh, t1, e1);             // A + nh = t1 + e1 exactly
        float d = __fadd_rn(t1, __fadd_rn(e1, nl));

        if (d < bd || (d == bd && c < bi)) { bd = d; bi = c; }
    }

    // combine the two halves (all lanes of a half agree)
    float od = __shfl_xor_sync(0xFFFFFFFFu, bd, 16);
    int   oc = __shfl_xor_sync(0xFFFFFFFFu, bi, 16);
    if (od < bd || (od == bd && oc < bi)) { bd = od; bi = oc; }

    if (lane == 0) g_final[r] = bi;
}

// ---------------- kernel 4: gather + outputs + partial losses + histogram
__global__ void k_quant(const float* __restrict__ latents,
                        const float* __restrict__ mask,
                        const float* __restrict__ cb,
                        float* __restrict__ out) {
    int warp = threadIdx.x >> 5;
    int lane = threadIdx.x & 31;
    int r = blockIdx.x * 8 + warp;

    int bi = g_final[r];

    const float4* L = reinterpret_cast<const float4*>(latents + (size_t)r * D);
    const float4* Q = reinterpret_cast<const float4*>(cb + (size_t)bi * D);
    float4* outq = reinterpret_cast<float4*>(out + OFF_Q  + (size_t)r * D);
    float4* outs = reinterpret_cast<float4*>(out + OFF_ST + (size_t)r * D);

    float ss = 0.0f;
    #pragma unroll
    for (int i = 0; i < 2; i++) {
        int idx = lane + 32 * i;
        float4 l = L[idx];
        float4 q = Q[idx];
        float4 st;
        st.x = __fadd_rn(l.x, __fsub_rn(q.x, l.x));
        st.y = __fadd_rn(l.y, __fsub_rn(q.y, l.y));
        st.z = __fadd_rn(l.z, __fsub_rn(q.z, l.z));
        st.w = __fadd_rn(l.w, __fsub_rn(q.w, l.w));
        outq[idx] = q;
        outs[idx] = st;
        float dx = l.x - q.x, dy = l.y - q.y, dz = l.z - q.z, dw = l.w - q.w;
        ss += dx * dx + dy * dy + dz * dz + dw * dw;
    }
    #pragma unroll
    for (int o = 16; o > 0; o >>= 1) ss += __shfl_xor_sync(0xFFFFFFFFu, ss, o);

    __shared__ float ws[8];
    if (lane == 0) {
        ws[warp] = ss;
        out[r] = (float)bi;
        atomicAdd(&g_hist[bi], mask[r]);
    }
    __syncthreads();
    if (threadIdx.x == 0) {
        float a = 0.0f;
        #pragma unroll
        for (int i = 0; i < 8; i++) a += ws[i];
        g_partial[blockIdx.x] = a;
    }
}

// ---------------- kernel 5: scalars (losses + perplexity) ----------------
__global__ void k_final(const float* __restrict__ mask, float* __restrict__ out) {
    __shared__ float red[256];
    int t = threadIdx.x;

    float s = 0.0f;
    for (int i = t; i < NR; i += 256) s += mask[i];
    red[t] = s; __syncthreads();
    for (int o = 128; o > 0; o >>= 1) { if (t < o) red[t] += red[t + o]; __syncthreads(); }
    float denom = fmaxf(red[0], 1.0f);
    __syncthreads();

    float q = 0.0f;
    for (int i = t; i < NQBLKS; i += 256) q += g_partial[i];
    red[t] = q; __syncthreads();
    for (int o = 128; o > 0; o >>= 1) { if (t < o) red[t] += red[t + o]; __syncthreads(); }
    float sq = red[0];
    __syncthreads();

    float e = 0.0f;
    for (int i = t; i < KC; i += 256) {
        float p = g_hist[i] / denom;
        e += p * logf(p + 1e-8f);
    }
    red[t] = e; __syncthreads();
    for (int o = 128; o > 0; o >>= 1) { if (t < o) red[t] += red[t + o]; __syncthreads(); }

    if (t == 0) {
        float mean = sq * (1.0f / 4194304.0f);
        out[OFF_SC + 0] = mean * 0.25f;
        out[OFF_SC + 1] = mean;
        out[OFF_SC + 2] = expf(-red[0]);
    }
}

extern "C" void kernel_launch(void* const* d_in, const int* in_sizes, int n_in,
                              void* d_out, int out_size) {
    const float* latents = (const float*)d_in[0];
    const float* mask    = (const float*)d_in[1];
    const float* cb      = (const float*)d_in[2];
    float* out = (float*)d_out;

    k_init<<<(KC + 255) / 256, 256>>>();
    k_xnorm<<<(NR * 32) / 256, 256>>>(latents);
    dim3 grid(ROWBLKS, SPLITS);
    k_argmin<<<grid, 256>>>(latents, cb);
    k_combine<<<NQBLKS, 256>>>(latents, cb);
    k_quant<<<NQBLKS, 256>>>(latents, mask, cb, out);
    k_final<<<1, 256>>>(mask, out);
}